// round 1
// baseline (speedup 1.0000x reference)
#include <cuda_runtime.h>
#include <math.h>

// Problem constants (fixed shapes for this bench)
#define BB 16
#define HH 256
#define WW 256
#define SS 24
#define PS (HH * WW)            // plane stride (per channel)
#define NPIX (BB * HH * WW)     // 1,048,576 pixels
#define NROWS (BB * HH)         // 4096 blocks, one per (b, h) row
#define EPSF 1e-6f
#define WGRAD 0.05f

// Per-block partial sums: .x = rot-loss sum, .y = grad-loss sum
__device__ float2 g_partials[NROWS];

__global__ __launch_bounds__(WW) void sym_rot_loss_kernel(
    const float* __restrict__ qp,
    const float* __restrict__ qt,
    const float* __restrict__ syms)
{
    // Stage sign-adjusted symmetry quaternions in shared memory.
    __shared__ float4 ss[SS];
    const int tid = threadIdx.x;
    if (tid < SS) {
        ss[tid] = make_float4( syms[tid * 4 + 0],
                              -syms[tid * 4 + 1],
                              -syms[tid * 4 + 2],
                              -syms[tid * 4 + 3]);
    }
    __syncthreads();

    const int row = blockIdx.x;        // row = b*HH + h
    const int b   = row >> 8;          // HH == 256
    const int h   = row & (HH - 1);
    const int w   = tid;               // WW == 256 threads

    const int base = (b * 4) * PS + h * WW + w;   // channel-0 element

    // ---- load the 4 channels of this pixel for pred & target ----
    float pv[4], tv[4];
#pragma unroll
    for (int c = 0; c < 4; c++) {
        pv[c] = __ldg(qp + base + c * PS);
        tv[c] = __ldg(qt + base + c * PS);
    }

    // ---- normalize both quaternions ----
    float np = sqrtf(pv[0]*pv[0] + pv[1]*pv[1] + pv[2]*pv[2] + pv[3]*pv[3]);
    float nt = sqrtf(tv[0]*tv[0] + tv[1]*tv[1] + tv[2]*tv[2] + tv[3]*tv[3]);
    float ip = 1.0f / fmaxf(np, EPSF);
    float it = 1.0f / fmaxf(nt, EPSF);
    float w1 = pv[0]*ip, x1 = pv[1]*ip, y1 = pv[2]*ip, z1 = pv[3]*ip;
    float w2 = tv[0]*it, x2 = tv[1]*it, y2 = tv[2]*it, z2 = tv[3]*it;

    // ---- relative quaternion r = conj-ish combination per reference ----
    float rw =  w2*w1 + x2*x1 + y2*y1 + z2*z1;
    float rx = -w2*x1 + x2*w1 - y2*z1 + z2*y1;
    float ry = -w2*y1 + x2*z1 + y2*w1 - z2*x1;
    float rz = -w2*z1 - x2*y1 + y2*x1 + z2*w1;

    // ---- max over 24 (sign-adjusted) symmetry dot products ----
    float maxw = 0.0f;
#pragma unroll
    for (int s = 0; s < SS; s++) {
        float4 v = ss[s];
        float d = rw*v.x + rx*v.y + ry*v.z + rz*v.w;
        maxw = fmaxf(maxw, fabsf(d));
    }
    maxw = fminf(maxw, 1.0f - EPSF);
    float rot = 2.0f * acosf(maxw);

    // ---- gradient-magnitude L1 term (all 4 channels) ----
    // At the right/bottom edge the padded gradient equals the previous
    // difference, which is the same value with flipped sign -> identical
    // after squaring, so we just flip the neighbor direction.
    const int dw = (w < WW - 1) ?  1 : -1;
    const int dh = (h < HH - 1) ? WW : -WW;

    float gsum = 0.0f;
#pragma unroll
    for (int c = 0; c < 4; c++) {
        const int idx = base + c * PS;
        float pr = __ldg(qp + idx + dw);
        float pd = __ldg(qp + idx + dh);
        float tr = __ldg(qt + idx + dw);
        float td = __ldg(qt + idx + dh);
        float gxp = pr - pv[c];
        float gyp = pd - pv[c];
        float gxt = tr - tv[c];
        float gyt = td - tv[c];
        float gp = sqrtf(gxp*gxp + gyp*gyp + EPSF);
        float gt = sqrtf(gxt*gxt + gyt*gyt + EPSF);
        gsum += fabsf(gp - gt);
    }

    // ---- block reduction of (rot, gsum) ----
    float r = rot, g = gsum;
#pragma unroll
    for (int o = 16; o > 0; o >>= 1) {
        r += __shfl_xor_sync(0xFFFFFFFFu, r, o);
        g += __shfl_xor_sync(0xFFFFFFFFu, g, o);
    }
    __shared__ float2 wsum[8];
    const int lane = tid & 31;
    const int warp = tid >> 5;
    if (lane == 0) wsum[warp] = make_float2(r, g);
    __syncthreads();
    if (warp == 0) {
        float2 v = (lane < 8) ? wsum[lane] : make_float2(0.0f, 0.0f);
        float rr = v.x, gg = v.y;
#pragma unroll
        for (int o = 4; o > 0; o >>= 1) {
            rr += __shfl_xor_sync(0xFFFFFFFFu, rr, o);
            gg += __shfl_xor_sync(0xFFFFFFFFu, gg, o);
        }
        if (lane == 0) g_partials[row] = make_float2(rr, gg);
    }
}

__global__ __launch_bounds__(1024) void finish_kernel(float* __restrict__ out)
{
    const int tid = threadIdx.x;
    float r = 0.0f, g = 0.0f;
#pragma unroll
    for (int i = tid; i < NROWS; i += 1024) {
        float2 v = g_partials[i];
        r += v.x;
        g += v.y;
    }
#pragma unroll
    for (int o = 16; o > 0; o >>= 1) {
        r += __shfl_xor_sync(0xFFFFFFFFu, r, o);
        g += __shfl_xor_sync(0xFFFFFFFFu, g, o);
    }
    __shared__ float2 wsum[32];
    const int lane = tid & 31;
    const int warp = tid >> 5;
    if (lane == 0) wsum[warp] = make_float2(r, g);
    __syncthreads();
    if (warp == 0) {
        float2 v = (lane < 32) ? wsum[lane] : make_float2(0.0f, 0.0f);
        float rr = v.x, gg = v.y;
#pragma unroll
        for (int o = 16; o > 0; o >>= 1) {
            rr += __shfl_xor_sync(0xFFFFFFFFu, rr, o);
            gg += __shfl_xor_sync(0xFFFFFFFFu, gg, o);
        }
        if (lane == 0) {
            float loss_rot  = rr / (float)NPIX;
            float loss_grad = gg / (float)(4 * NPIX);
            out[0] = loss_rot + WGRAD * loss_grad;
        }
    }
}

extern "C" void kernel_launch(void* const* d_in, const int* in_sizes, int n_in,
                              void* d_out, int out_size)
{
    const float* qp   = (const float*)d_in[0];
    const float* qt   = (const float*)d_in[1];
    const float* syms = (const float*)d_in[2];
    float* out = (float*)d_out;

    sym_rot_loss_kernel<<<NROWS, WW>>>(qp, qt, syms);
    finish_kernel<<<1, 1024>>>(out);
}

// round 2
// speedup vs baseline: 1.4716x; 1.4716x over previous
#include <cuda_runtime.h>
#include <math.h>

// Fixed problem shapes
#define BB 16
#define HH 256
#define WW 256
#define SS 24
#define PS (HH * WW)             // per-channel plane stride
#define NPIX (BB * HH * WW)      // 1,048,576
#define NBLK 1024                // blocks: 4 rows per block
#define EPSF 1e-6f
#define WGRAD 0.05f

typedef unsigned long long ull;

__device__ float2 g_partials[NBLK];
__device__ unsigned int g_count = 0;

// ---------- packed f32x2 + MUFU helpers ----------
__device__ __forceinline__ ull pack2(float lo, float hi) {
    ull r; asm("mov.b64 %0, {%1, %2};" : "=l"(r) : "f"(lo), "f"(hi)); return r;
}
__device__ __forceinline__ void unpack2(ull v, float& lo, float& hi) {
    asm("mov.b64 {%0, %1}, %2;" : "=f"(lo), "=f"(hi) : "l"(v));
}
__device__ __forceinline__ ull fma2(ull a, ull b, ull c) {
    ull r; asm("fma.rn.f32x2 %0, %1, %2, %3;" : "=l"(r) : "l"(a), "l"(b), "l"(c)); return r;
}
__device__ __forceinline__ ull mul2(ull a, ull b) {
    ull r; asm("mul.rn.f32x2 %0, %1, %2;" : "=l"(r) : "l"(a), "l"(b)); return r;
}
__device__ __forceinline__ float sqrta(float x) {
    float r; asm("sqrt.approx.f32 %0, %1;" : "=f"(r) : "f"(x)); return r;
}
__device__ __forceinline__ float rsqrta(float x) {
    float r; asm("rsqrt.approx.f32 %0, %1;" : "=f"(r) : "f"(x)); return r;
}

// acos on [0,1]: deg-7 minimax (A&S 4.4.46 family), abs err ~2e-8
__device__ __forceinline__ float acos_fast(float x) {
    float p = fmaf(x, -0.0012624911f, 0.0066700901f);
    p = fmaf(x, p, -0.0170881256f);
    p = fmaf(x, p,  0.0308918810f);
    p = fmaf(x, p, -0.0501743046f);
    p = fmaf(x, p,  0.0889789874f);
    p = fmaf(x, p, -0.2145988016f);
    p = fmaf(x, p,  1.5707963050f);
    return sqrta(1.0f - x) * p;
}

__global__ __launch_bounds__(256) void fused_loss_kernel(
    const float* __restrict__ qp,
    const float* __restrict__ qt,
    const float* __restrict__ syms,
    float* __restrict__ out)
{
    // Pre-packed sign-adjusted symmetry splats: s2[s][k] = {comp, comp} as f32x2
    __shared__ ull s2[SS][4];
    __shared__ float2 wsum[8];
    __shared__ bool amLast;

    const int tid = threadIdx.x;
    if (tid < SS) {
        float a =  syms[tid * 4 + 0];
        float b = -syms[tid * 4 + 1];
        float c = -syms[tid * 4 + 2];
        float d = -syms[tid * 4 + 3];
        s2[tid][0] = pack2(a, a);
        s2[tid][1] = pack2(b, b);
        s2[tid][2] = pack2(c, c);
        s2[tid][3] = pack2(d, d);
    }
    __syncthreads();

    // 4 rows per block, 64 threads per row, 4 pixels per thread (float4)
    const int row = (blockIdx.x << 2) + (tid >> 6);   // row = b*HH + h
    const int t   = tid & 63;
    const int b   = row >> 8;
    const int h   = row & (HH - 1);
    const int base = b * 4 * PS + h * WW + (t << 2);
    const int dh  = (h < HH - 1) ? WW : -WW;          // mirrored edge: |diff| identical
    const bool hasr = (t < 63);

    float4 P[4], T[4], PD[4], TD[4];
    float PR[4], TR[4];
#pragma unroll
    for (int c = 0; c < 4; c++) {
        const float* pp = qp + base + c * PS;
        const float* tt = qt + base + c * PS;
        P[c]  = __ldg((const float4*)pp);
        T[c]  = __ldg((const float4*)tt);
        PD[c] = __ldg((const float4*)(pp + dh));
        TD[c] = __ldg((const float4*)(tt + dh));
        PR[c] = hasr ? __ldg(pp + 4) : 0.0f;
        TR[c] = hasr ? __ldg(tt + 4) : 0.0f;
    }

    float rw[4], rx[4], ry[4], rz[4];
    float gsum = 0.0f;
#pragma unroll
    for (int i = 0; i < 4; i++) {
        float pv[4], tv[4];
#pragma unroll
        for (int c = 0; c < 4; c++) {
            pv[c] = ((const float*)&P[c])[i];
            tv[c] = ((const float*)&T[c])[i];
        }
        // normalize (rsqrt.approx; norms are O(1), eps guard unreachable)
        float dp = fmaf(pv[0], pv[0], fmaf(pv[1], pv[1], fmaf(pv[2], pv[2], pv[3]*pv[3])));
        float dt = fmaf(tv[0], tv[0], fmaf(tv[1], tv[1], fmaf(tv[2], tv[2], tv[3]*tv[3])));
        float ip = rsqrta(dp);
        float it = rsqrta(dt);
        float w1 = pv[0]*ip, x1 = pv[1]*ip, y1 = pv[2]*ip, z1 = pv[3]*ip;
        float w2 = tv[0]*it, x2 = tv[1]*it, y2 = tv[2]*it, z2 = tv[3]*it;
        rw[i] =  w2*w1 + x2*x1 + y2*y1 + z2*z1;
        rx[i] = -w2*x1 + x2*w1 - y2*z1 + z2*y1;
        ry[i] = -w2*y1 + x2*z1 + y2*w1 - z2*x1;
        rz[i] = -w2*z1 - x2*y1 + y2*x1 + z2*w1;

        // gradient-magnitude L1 term
#pragma unroll
        for (int c = 0; c < 4; c++) {
            float pr = (i < 3) ? ((const float*)&P[c])[i + 1]
                               : (hasr ? PR[c] : ((const float*)&P[c])[2]);
            float tr = (i < 3) ? ((const float*)&T[c])[i + 1]
                               : (hasr ? TR[c] : ((const float*)&T[c])[2]);
            float pd = ((const float*)&PD[c])[i];
            float td = ((const float*)&TD[c])[i];
            float gxp = pr - pv[c], gyp = pd - pv[c];
            float gxt = tr - tv[c], gyt = td - tv[c];
            float gp = sqrta(fmaf(gxp, gxp, fmaf(gyp, gyp, EPSF)));
            float gt = sqrta(fmaf(gxt, gxt, fmaf(gyt, gyt, EPSF)));
            gsum += fabsf(gp - gt);
        }
    }

    // ---- 24-symmetry max|dot| on packed f32x2 (2 pixels per op) ----
    ull rw01 = pack2(rw[0], rw[1]), rw23 = pack2(rw[2], rw[3]);
    ull rx01 = pack2(rx[0], rx[1]), rx23 = pack2(rx[2], rx[3]);
    ull ry01 = pack2(ry[0], ry[1]), ry23 = pack2(ry[2], ry[3]);
    ull rz01 = pack2(rz[0], rz[1]), rz23 = pack2(rz[2], rz[3]);
    const ull ABS2 = 0x7FFFFFFF7FFFFFFFULL;
    float m0 = 0.0f, m1 = 0.0f, m2 = 0.0f, m3 = 0.0f;
#pragma unroll
    for (int s = 0; s < SS; s++) {
        ull vx = s2[s][0], vy = s2[s][1], vz = s2[s][2], vw = s2[s][3];
        ull d01 = fma2(rw01, vx, fma2(rx01, vy, fma2(ry01, vz, mul2(rz01, vw)))) & ABS2;
        ull d23 = fma2(rw23, vx, fma2(rx23, vy, fma2(ry23, vz, mul2(rz23, vw)))) & ABS2;
        float a, bb;
        unpack2(d01, a, bb); m0 = fmaxf(m0, a); m1 = fmaxf(m1, bb);
        unpack2(d23, a, bb); m2 = fmaxf(m2, a); m3 = fmaxf(m3, bb);
    }
    const float CL = 1.0f - EPSF;
    float rot = acos_fast(fminf(m0, CL)) + acos_fast(fminf(m1, CL))
              + acos_fast(fminf(m2, CL)) + acos_fast(fminf(m3, CL));
    rot *= 2.0f;

    // ---- block reduction ----
    float r = rot, g = gsum;
#pragma unroll
    for (int o = 16; o > 0; o >>= 1) {
        r += __shfl_xor_sync(0xFFFFFFFFu, r, o);
        g += __shfl_xor_sync(0xFFFFFFFFu, g, o);
    }
    const int lane = tid & 31;
    const int warp = tid >> 5;
    if (lane == 0) wsum[warp] = make_float2(r, g);
    __syncthreads();
    if (warp == 0) {
        float2 v = (lane < 8) ? wsum[lane] : make_float2(0.0f, 0.0f);
        float rr = v.x, gg = v.y;
#pragma unroll
        for (int o = 4; o > 0; o >>= 1) {
            rr += __shfl_xor_sync(0xFFFFFFFFu, rr, o);
            gg += __shfl_xor_sync(0xFFFFFFFFu, gg, o);
        }
        if (lane == 0) {
            g_partials[blockIdx.x] = make_float2(rr, gg);
            __threadfence();
            unsigned int c = atomicAdd(&g_count, 1u);
            amLast = (c == NBLK - 1);
        }
    }
    __syncthreads();

    // ---- last block: grid-wide finish (deterministic fixed-order sum) ----
    if (amLast) {
        float r2 = 0.0f, g2 = 0.0f;
#pragma unroll
        for (int i = tid; i < NBLK; i += 256) {
            float2 v = __ldcg(&g_partials[i]);
            r2 += v.x; g2 += v.y;
        }
#pragma unroll
        for (int o = 16; o > 0; o >>= 1) {
            r2 += __shfl_xor_sync(0xFFFFFFFFu, r2, o);
            g2 += __shfl_xor_sync(0xFFFFFFFFu, g2, o);
        }
        if (lane == 0) wsum[warp] = make_float2(r2, g2);
        __syncthreads();
        if (tid == 0) {
            float rr = 0.0f, gg = 0.0f;
#pragma unroll
            for (int i = 0; i < 8; i++) { rr += wsum[i].x; gg += wsum[i].y; }
            out[0] = rr / (float)NPIX + WGRAD * (gg / (float)(4 * NPIX));
            g_count = 0;   // reset for next graph replay
        }
    }
}

extern "C" void kernel_launch(void* const* d_in, const int* in_sizes, int n_in,
                              void* d_out, int out_size)
{
    const float* qp   = (const float*)d_in[0];
    const float* qt   = (const float*)d_in[1];
    const float* syms = (const float*)d_in[2];
    float* out = (float*)d_out;

    fused_loss_kernel<<<NBLK, 256>>>(qp, qt, syms, out);
}